// round 1
// baseline (speedup 1.0000x reference)
#include <cuda_runtime.h>
#include <cstdint>
#include <cstddef>

#define BB 64
#define SS 2048
#define DIN 512
#define HH 1024
#define SPLITS 8

#define NEG_INF __int_as_float(0xff800000)

// ---------------- scratch (no allocations allowed) ----------------
__device__ float          g_x[BB * HH];                 // inp@W + b
__device__ unsigned char  g_mask[BB * SS];              // canonical mask (1 = masked)
__device__ float          g_score[BB * SS];             // raw scores (-inf where masked)
__device__ float          g_acc[BB * SPLITS * HH];      // split partial weighted sums
__device__ float2         g_ml[BB * SPLITS];            // split partial (max, sumexp)

// ---------------- helpers ----------------
__device__ __forceinline__ float tanh_acc(float x) {
    // accurate enough: tanh(x) = 1 - 2/(exp(2x)+1); __expf ~2ulp, abs err ~1e-7
    float e = __expf(2.0f * x);
    return 1.0f - __fdividef(2.0f, e + 1.0f);
}

// ---------------- kernel 0: detect mask encoding + canonicalize ----------------
// bool masks may be serialized as int32 {0,1}, float32 {0,1.0f}, or raw bytes.
// Detection: scan first 1024 words (4KB, safe under every layout: byte layout is 128KB).
__global__ void mask_norm_kernel(const void* __restrict__ mraw) {
    const unsigned* w = (const unsigned*)mraw;
    int t = threadIdx.x;
    int notInt = 0, notFloat = 0;
    for (int i = t; i < 1024; i += 256) {
        unsigned x = w[i];
        notInt   |= (x > 1u);
        notFloat |= (x != 0u && x != 0x3F800000u);
    }
    notInt   = __syncthreads_or(notInt);
    notFloat = __syncthreads_or(notFloat);
    // mode 0: int32, mode 1: float32, mode 2: bytes
    int mode = notInt ? (notFloat ? 2 : 1) : 0;

    const int per_block = (BB * SS) / 128;  // 1024
    int base = blockIdx.x * per_block;
    for (int i = base + t; i < base + per_block; i += 256) {
        unsigned char v;
        if (mode == 0)      v = (((const int*)mraw)[i] != 0);
        else if (mode == 1) v = (((const float*)mraw)[i] != 0.0f);
        else                v = (((const unsigned char*)mraw)[i] != 0);
        g_mask[i] = v;
    }
}

// ---------------- kernel 1: x = inp @ W + b  (64x1024, K=512) ----------------
// 128 CTAs, each owns 8 H-columns for all 64 batches. W slab (512x8 = 16KB) in smem.
__global__ __launch_bounds__(256) void xgemm_kernel(const float* __restrict__ inp,
                                                    const float* __restrict__ Wm,
                                                    const float* __restrict__ bias) {
    __shared__ float ws[DIN * 8];
    int h0 = blockIdx.x * 8;
    int t  = threadIdx.x;
    for (int idx = t; idx < DIN * 8; idx += 256) {
        int k = idx >> 3, j = idx & 7;
        ws[idx] = Wm[k * HH + h0 + j];
    }
    __syncthreads();

    int b  = t >> 2;
    int j0 = (t & 3) * 2;
    float acc0 = bias[h0 + j0];
    float acc1 = bias[h0 + j0 + 1];
    const float4* ip = (const float4*)(inp + b * DIN);
#pragma unroll 4
    for (int k4 = 0; k4 < DIN / 4; k4++) {
        float4 p = __ldg(&ip[k4]);
        int kb = k4 * 32 + j0;
        float2 w0 = *(const float2*)&ws[kb];
        float2 w1 = *(const float2*)&ws[kb + 8];
        float2 w2 = *(const float2*)&ws[kb + 16];
        float2 w3 = *(const float2*)&ws[kb + 24];
        acc0 = fmaf(p.x, w0.x, acc0); acc1 = fmaf(p.x, w0.y, acc1);
        acc0 = fmaf(p.y, w1.x, acc0); acc1 = fmaf(p.y, w1.y, acc1);
        acc0 = fmaf(p.z, w2.x, acc0); acc1 = fmaf(p.z, w2.y, acc1);
        acc0 = fmaf(p.w, w3.x, acc0); acc1 = fmaf(p.w, w3.y, acc1);
    }
    g_x[b * HH + h0 + j0]     = acc0;
    g_x[b * HH + h0 + j0 + 1] = acc1;
}

// ---------------- kernel 2: fused scores + online softmax + weighted sum ----
// Grid: B*SPLITS CTAs of 256 threads (8 warps). Warp owns 32 contiguous rows.
// Per-lane register state: x[32], v[32], acc[32] as float4[8], h = g*128 + ln*4.
// Masked rows: score := -inf, context row load SKIPPED entirely.
__global__ __launch_bounds__(256, 1) void pass1_kernel(const float* __restrict__ ctx,
                                                       const float* __restrict__ v) {
    int b    = blockIdx.x >> 3;
    int sp   = blockIdx.x & (SPLITS - 1);
    int warp = threadIdx.x >> 5;
    int ln   = threadIdx.x & 31;
    int srow = sp * (SS / SPLITS) + warp * 32;

    float4 xv[8], vv[8], acc[8];
    const float4* xr = (const float4*)(g_x + b * HH);
    const float4* vr = (const float4*)v;
#pragma unroll
    for (int g = 0; g < 8; g++) {
        xv[g]  = xr[g * 32 + ln];
        vv[g]  = vr[g * 32 + ln];
        acc[g] = make_float4(0.f, 0.f, 0.f, 0.f);
    }
    float m = NEG_INF, l = 0.f;

    int gsrow = b * SS + srow;
    unsigned char mk = g_mask[gsrow + ln];
    unsigned bits = __ballot_sync(0xffffffffu, mk == 0);   // set bit = unmasked row
    if (mk) g_score[gsrow + ln] = NEG_INF;                 // masked rows: -inf now

    const float* cbase = ctx + ((size_t)gsrow) * HH;
    unsigned rem = bits;
    while (rem) {
        int s = __ffs((int)rem) - 1;
        rem &= rem - 1;
        const float4* crow = (const float4*)(cbase + (size_t)s * HH);
        float4 c[8];
#pragma unroll
        for (int g = 0; g < 8; g++) c[g] = __ldg(&crow[g * 32 + ln]);

        float part = 0.f;
#pragma unroll
        for (int g = 0; g < 8; g++) {
            float4 a = xv[g], cc = c[g], vg = vv[g];
            part = fmaf(tanh_acc(a.x + cc.x), vg.x, part);
            part = fmaf(tanh_acc(a.y + cc.y), vg.y, part);
            part = fmaf(tanh_acc(a.z + cc.z), vg.z, part);
            part = fmaf(tanh_acc(a.w + cc.w), vg.w, part);
        }
#pragma unroll
        for (int off = 16; off; off >>= 1)
            part += __shfl_xor_sync(0xffffffffu, part, off);

        if (ln == 0) g_score[gsrow + s] = part;

        if (part <= m) {                       // common case: 1 FMA per element
            float p = __expf(part - m);
            l += p;
#pragma unroll
            for (int g = 0; g < 8; g++) {
                acc[g].x = fmaf(c[g].x, p, acc[g].x);
                acc[g].y = fmaf(c[g].y, p, acc[g].y);
                acc[g].z = fmaf(c[g].z, p, acc[g].z);
                acc[g].w = fmaf(c[g].w, p, acc[g].w);
            }
        } else {                               // new max (~ln(32) times per warp)
            float sc = __expf(m - part);
            l = fmaf(l, sc, 1.0f);
#pragma unroll
            for (int g = 0; g < 8; g++) {
                acc[g].x = fmaf(acc[g].x, sc, c[g].x);
                acc[g].y = fmaf(acc[g].y, sc, c[g].y);
                acc[g].z = fmaf(acc[g].z, sc, c[g].z);
                acc[g].w = fmaf(acc[g].w, sc, c[g].w);
            }
            m = part;
        }
    }

    // ---- combine 8 warps within CTA ----
    __shared__ float s_acc[8][HH];   // 32 KB
    __shared__ float s_m[8], s_l[8];
#pragma unroll
    for (int g = 0; g < 8; g++)
        *(float4*)&s_acc[warp][g * 128 + ln * 4] = acc[g];
    if (ln == 0) { s_m[warp] = m; s_l[warp] = l; }
    __syncthreads();

    float M = s_m[0];
#pragma unroll
    for (int i = 1; i < 8; i++) M = fmaxf(M, s_m[i]);
    float f[8];
    float L = 0.f;
#pragma unroll
    for (int i = 0; i < 8; i++) {
        f[i] = (s_m[i] == NEG_INF) ? 0.f : __expf(s_m[i] - M);
        L = fmaf(s_l[i], f[i], L);
    }

    int t = threadIdx.x;
    float4 sum = make_float4(0.f, 0.f, 0.f, 0.f);
#pragma unroll
    for (int i = 0; i < 8; i++) {
        float4 a = *(const float4*)&s_acc[i][t * 4];
        sum.x = fmaf(a.x, f[i], sum.x);
        sum.y = fmaf(a.y, f[i], sum.y);
        sum.z = fmaf(a.z, f[i], sum.z);
        sum.w = fmaf(a.w, f[i], sum.w);
    }
    *(float4*)&g_acc[(b * SPLITS + sp) * HH + t * 4] = sum;
    if (t == 0) g_ml[b * SPLITS + sp] = make_float2(M, L);
}

// ---------------- kernel 3: merge splits, emit attn_applied + attn_weights ---
__global__ __launch_bounds__(256) void combine_kernel(float* __restrict__ out_applied,
                                                      float* __restrict__ out_w) {
    int b = blockIdx.x;
    int t = threadIdx.x;

    float2 ml[SPLITS];
#pragma unroll
    for (int i = 0; i < SPLITS; i++) ml[i] = g_ml[b * SPLITS + i];
    float M = ml[0].x;
#pragma unroll
    for (int i = 1; i < SPLITS; i++) M = fmaxf(M, ml[i].x);
    float f[SPLITS];
    float L = 0.f;
#pragma unroll
    for (int i = 0; i < SPLITS; i++) {
        f[i] = (ml[i].x == NEG_INF) ? 0.f : __expf(ml[i].x - M);
        L = fmaf(ml[i].y, f[i], L);
    }
    float invL = 1.0f / L;

    float4 sum = make_float4(0.f, 0.f, 0.f, 0.f);
#pragma unroll
    for (int i = 0; i < SPLITS; i++) {
        float4 a = *(const float4*)&g_acc[(b * SPLITS + i) * HH + t * 4];
        sum.x = fmaf(a.x, f[i], sum.x);
        sum.y = fmaf(a.y, f[i], sum.y);
        sum.z = fmaf(a.z, f[i], sum.z);
        sum.w = fmaf(a.w, f[i], sum.w);
    }
    sum.x *= invL; sum.y *= invL; sum.z *= invL; sum.w *= invL;
    ((float4*)out_applied)[b * 256 + t] = sum;

    for (int s = t; s < SS; s += 256) {
        float sc = g_score[b * SS + s];            // -inf on masked -> exact 0
        out_w[b * SS + s] = __expf(sc - M) * invL;
    }
}

// ---------------- launch ----------------
extern "C" void kernel_launch(void* const* d_in, const int* in_sizes, int n_in,
                              void* d_out, int out_size) {
    const float* inp  = (const float*)d_in[0];
    // d_in[1] = hidden (unused by the reference computation)
    const float* ctx  = (const float*)d_in[2];
    const void*  mask = d_in[3];
    const float* Wm   = (const float*)d_in[4];
    const float* bias = (const float*)d_in[5];
    const float* v    = (const float*)d_in[6];
    float* out = (float*)d_out;

    mask_norm_kernel<<<128, 256>>>(mask);
    xgemm_kernel<<<128, 256>>>(inp, Wm, bias);
    pass1_kernel<<<BB * SPLITS, 256>>>(ctx, v);
    combine_kernel<<<BB, 256>>>(out, out + BB * HH);
}

// round 2
// speedup vs baseline: 1.0759x; 1.0759x over previous
#include <cuda_runtime.h>
#include <cstdint>
#include <cstddef>

#define BB 64
#define SS 2048
#define DIN 512
#define HH 1024
#define SPLITS 16            // tiles per batch; 1024 tiles total
#define NTILES (BB * SPLITS)
#define ROWS_PER_TILE (SS / SPLITS)   // 128
#define ROWS_PER_WARP (ROWS_PER_TILE / 8)  // 16

#define NEG_INF __int_as_float(0xff800000)

// ---------------- scratch (no allocations allowed) ----------------
__device__ float          g_x[BB * HH];                 // inp@W + b
__device__ unsigned char  g_mask[BB * SS];              // canonical mask (1 = masked)
__device__ float          g_score[BB * SS];             // raw scores (-inf where masked)
__device__ float          g_acc[BB * SPLITS * HH];      // tile partial weighted sums
__device__ float          g_l[BB * SPLITS];             // tile partial sum-of-exp
__device__ unsigned       g_ticket;                     // persistent work queue

// ---------------- helpers ----------------
__device__ __forceinline__ float tanh_acc(float x) {
    // tanh(x) = 1 - 2/(exp(2x)+1); __expf+__fdividef = 2 MUFU, abs err ~1e-7
    float e = __expf(2.0f * x);
    return 1.0f - __fdividef(2.0f, e + 1.0f);
}

// ---------------- kernel 0: mask canonicalize + ticket reset ----------------
__global__ void mask_norm_kernel(const void* __restrict__ mraw) {
    if (blockIdx.x == 0 && threadIdx.x == 0) g_ticket = 0;
    const unsigned* w = (const unsigned*)mraw;
    int t = threadIdx.x;
    int notInt = 0, notFloat = 0;
    for (int i = t; i < 1024; i += 256) {
        unsigned x = w[i];
        notInt   |= (x > 1u);
        notFloat |= (x != 0u && x != 0x3F800000u);
    }
    notInt   = __syncthreads_or(notInt);
    notFloat = __syncthreads_or(notFloat);
    int mode = notInt ? (notFloat ? 2 : 1) : 0;   // 0:int32  1:float32  2:bytes

    const int per_block = (BB * SS) / 128;
    int base = blockIdx.x * per_block;
    for (int i = base + t; i < base + per_block; i += 256) {
        unsigned char v;
        if (mode == 0)      v = (((const int*)mraw)[i] != 0);
        else if (mode == 1) v = (((const float*)mraw)[i] != 0.0f);
        else                v = (((const unsigned char*)mraw)[i] != 0);
        g_mask[i] = v;
    }
}

// ---------------- kernel 1: x = inp @ W + b  (64x1024, K=512) ----------------
__global__ __launch_bounds__(256) void xgemm_kernel(const float* __restrict__ inp,
                                                    const float* __restrict__ Wm,
                                                    const float* __restrict__ bias) {
    __shared__ float ws[DIN * 8];
    int h0 = blockIdx.x * 8;
    int t  = threadIdx.x;
    for (int idx = t; idx < DIN * 8; idx += 256) {
        int k = idx >> 3, j = idx & 7;
        ws[idx] = Wm[k * HH + h0 + j];
    }
    __syncthreads();

    int b  = t >> 2;
    int j0 = (t & 3) * 2;
    float acc0 = bias[h0 + j0];
    float acc1 = bias[h0 + j0 + 1];
    const float4* ip = (const float4*)(inp + b * DIN);
#pragma unroll 4
    for (int k4 = 0; k4 < DIN / 4; k4++) {
        float4 p = __ldg(&ip[k4]);
        int kb = k4 * 32 + j0;
        float2 w0 = *(const float2*)&ws[kb];
        float2 w1 = *(const float2*)&ws[kb + 8];
        float2 w2 = *(const float2*)&ws[kb + 16];
        float2 w3 = *(const float2*)&ws[kb + 24];
        acc0 = fmaf(p.x, w0.x, acc0); acc1 = fmaf(p.x, w0.y, acc1);
        acc0 = fmaf(p.y, w1.x, acc0); acc1 = fmaf(p.y, w1.y, acc1);
        acc0 = fmaf(p.z, w2.x, acc0); acc1 = fmaf(p.z, w2.y, acc1);
        acc0 = fmaf(p.w, w3.x, acc0); acc1 = fmaf(p.w, w3.y, acc1);
    }
    g_x[b * HH + h0 + j0]     = acc0;
    g_x[b * HH + h0 + j0 + 1] = acc1;
}

// ---------------- kernel 2: fused scores + exp-sum + weighted sum -----------
// Persistent CTAs; tickets over 1024 tiles of (batch, 128 rows).
// Warp owns 16 rows; masked rows skipped entirely; row loads double-buffered.
__device__ __forceinline__ void loadrow(float4 (&c)[8], const float* cbase,
                                        int s, int ln) {
    const float4* crow = (const float4*)(cbase + (size_t)s * HH);
#pragma unroll
    for (int g = 0; g < 8; g++) c[g] = __ldg(&crow[g * 32 + ln]);
}

__global__ __launch_bounds__(256, 1) void pass1_kernel(const float* __restrict__ ctx,
                                                       const float* __restrict__ v) {
    __shared__ float    s_acc[8][HH];   // 32 KB
    __shared__ float    s_l[8];
    __shared__ unsigned s_tile;

    int t    = threadIdx.x;
    int warp = t >> 5;
    int ln   = t & 31;

    float4 vv[8];
    const float4* vr = (const float4*)v;
#pragma unroll
    for (int g = 0; g < 8; g++) vv[g] = vr[g * 32 + ln];

    while (true) {
        if (t == 0) s_tile = atomicAdd(&g_ticket, 1u);
        __syncthreads();
        unsigned tile = s_tile;
        if (tile >= NTILES) break;

        int b  = tile >> 4;          // SPLITS = 16
        int sp = tile & (SPLITS - 1);

        float4 xv[8], acc[8];
        const float4* xr = (const float4*)(g_x + b * HH);
#pragma unroll
        for (int g = 0; g < 8; g++) {
            xv[g]  = xr[g * 32 + ln];
            acc[g] = make_float4(0.f, 0.f, 0.f, 0.f);
        }
        float l = 0.f;

        int gsrow = b * SS + sp * ROWS_PER_TILE + warp * ROWS_PER_WARP;
        unsigned char mk = (ln < ROWS_PER_WARP) ? g_mask[gsrow + ln] : 1;
        unsigned bits = __ballot_sync(0xffffffffu, mk == 0);
        if (ln < ROWS_PER_WARP && mk) g_score[gsrow + ln] = NEG_INF;

        const float* cbase = ctx + (size_t)gsrow * HH;
        unsigned rem = bits;
        if (rem) {
            int s_cur = __ffs((int)rem) - 1; rem &= rem - 1;
            float4 cc[8];
            loadrow(cc, cbase, s_cur, ln);
            while (true) {
                int s_nxt = -1;
                float4 cn[8];
                if (rem) {                       // prefetch next unmasked row
                    s_nxt = __ffs((int)rem) - 1; rem &= rem - 1;
                    loadrow(cn, cbase, s_nxt, ln);
                }
                float part = 0.f;
#pragma unroll
                for (int g = 0; g < 8; g++) {
                    float4 a = xv[g], c = cc[g], vg = vv[g];
                    part = fmaf(tanh_acc(a.x + c.x), vg.x, part);
                    part = fmaf(tanh_acc(a.y + c.y), vg.y, part);
                    part = fmaf(tanh_acc(a.z + c.z), vg.z, part);
                    part = fmaf(tanh_acc(a.w + c.w), vg.w, part);
                }
#pragma unroll
                for (int off = 16; off; off >>= 1)
                    part += __shfl_xor_sync(0xffffffffu, part, off);

                if (ln == 0) g_score[gsrow + s_cur] = part;
                float p = __expf(part);          // fixed reference point M=0:
                l += p;                          // |score| provably < 40, exp safe
#pragma unroll
                for (int g = 0; g < 8; g++) {
                    acc[g].x = fmaf(cc[g].x, p, acc[g].x);
                    acc[g].y = fmaf(cc[g].y, p, acc[g].y);
                    acc[g].z = fmaf(cc[g].z, p, acc[g].z);
                    acc[g].w = fmaf(cc[g].w, p, acc[g].w);
                }
                if (s_nxt < 0) break;
#pragma unroll
                for (int g = 0; g < 8; g++) cc[g] = cn[g];
                s_cur = s_nxt;
            }
        }

        // ---- combine 8 warps within CTA ----
#pragma unroll
        for (int g = 0; g < 8; g++)
            *(float4*)&s_acc[warp][g * 128 + ln * 4] = acc[g];
        if (ln == 0) s_l[warp] = l;
        __syncthreads();

        float L = 0.f;
#pragma unroll
        for (int i = 0; i < 8; i++) L += s_l[i];

        float4 sum = make_float4(0.f, 0.f, 0.f, 0.f);
#pragma unroll
        for (int i = 0; i < 8; i++) {
            float4 a = *(const float4*)&s_acc[i][t * 4];
            sum.x += a.x; sum.y += a.y; sum.z += a.z; sum.w += a.w;
        }
        *(float4*)&g_acc[(size_t)tile * HH + t * 4] = sum;
        if (t == 0) g_l[tile] = L;
        __syncthreads();   // protect s_acc/s_l before next tile
    }
}

// ---------------- kernel 3: merge tiles, emit attn_applied + attn_weights ---
// grid = 64 * 8; CTA (b, part) handles 128 applied elems + 256 weights.
__global__ __launch_bounds__(256) void combine_kernel(float* __restrict__ out_applied,
                                                      float* __restrict__ out_w) {
    int b    = blockIdx.x >> 3;
    int part = blockIdx.x & 7;
    int t    = threadIdx.x;

    float L = 0.f;
#pragma unroll
    for (int i = 0; i < SPLITS; i++) L += g_l[b * SPLITS + i];
    float invL = 1.0f / L;

    if (t < 128) {
        int h = part * 128 + t;
        float s = 0.f;
#pragma unroll
        for (int i = 0; i < SPLITS; i++)
            s += g_acc[(size_t)(b * SPLITS + i) * HH + h];
        out_applied[b * HH + h] = s * invL;
    }
    int s_idx = part * 256 + t;
    float sc = g_score[b * SS + s_idx];            // -inf on masked -> exact 0
    out_w[b * SS + s_idx] = __expf(sc) * invL;
}

// ---------------- launch ----------------
extern "C" void kernel_launch(void* const* d_in, const int* in_sizes, int n_in,
                              void* d_out, int out_size) {
    const float* inp  = (const float*)d_in[0];
    // d_in[1] = hidden (unused by the reference computation)
    const float* ctx  = (const float*)d_in[2];
    const void*  mask = d_in[3];
    const float* Wm   = (const float*)d_in[4];
    const float* bias = (const float*)d_in[5];
    const float* v    = (const float*)d_in[6];
    float* out = (float*)d_out;

    mask_norm_kernel<<<128, 256>>>(mask);
    xgemm_kernel<<<128, 256>>>(inp, Wm, bias);
    pass1_kernel<<<152, 256>>>(ctx, v);
    combine_kernel<<<BB * 8, 256>>>(out, out + BB * HH);
}

// round 3
// speedup vs baseline: 1.2172x; 1.1314x over previous
#include <cuda_runtime.h>
#include <cstdint>
#include <cstddef>

#define BB 64
#define SS 2048
#define DIN 512
#define HH 1024
#define SPLITS 16                      // tiles per batch; 1024 tiles total
#define NTILES (BB * SPLITS)
#define ROWS_PER_TILE (SS / SPLITS)    // 128
#define ROWS_PER_GRP 16                // rows per warp-pair

#define NEG_INF __int_as_float(0xff800000)

// ---------------- scratch (no allocations allowed) ----------------
__device__ float          g_x[BB * HH];                 // inp@W + b
__device__ unsigned char  g_mask[BB * SS];              // canonical mask (1 = masked)
__device__ float          g_score[BB * SS];             // raw scores (-inf where masked)
__device__ float          g_acc[BB * SPLITS * HH];      // tile partial weighted sums
__device__ float          g_l[BB * SPLITS];             // tile partial sum-of-exp
__device__ unsigned       g_ticket;                     // persistent work queue

// ---------------- helpers ----------------
__device__ __forceinline__ float tanh_acc(float x) {
    // tanh(x) = 1 - 2/(exp(2x)+1); __expf+__fdividef = 2 MUFU, abs err ~1e-7
    float e = __expf(2.0f * x);
    return 1.0f - __fdividef(2.0f, e + 1.0f);
}

// ---------------- kernel 0: mask canonicalize + ticket reset ----------------
__global__ void mask_norm_kernel(const void* __restrict__ mraw) {
    if (blockIdx.x == 0 && threadIdx.x == 0) g_ticket = 0;
    const unsigned* w = (const unsigned*)mraw;
    int t = threadIdx.x;
    int notInt = 0, notFloat = 0;
    for (int i = t; i < 1024; i += 256) {
        unsigned x = w[i];
        notInt   |= (x > 1u);
        notFloat |= (x != 0u && x != 0x3F800000u);
    }
    notInt   = __syncthreads_or(notInt);
    notFloat = __syncthreads_or(notFloat);
    int mode = notInt ? (notFloat ? 2 : 1) : 0;   // 0:int32  1:float32  2:bytes

    const int per_block = (BB * SS) / 128;
    int base = blockIdx.x * per_block;
    for (int i = base + t; i < base + per_block; i += 256) {
        unsigned char v;
        if (mode == 0)      v = (((const int*)mraw)[i] != 0);
        else if (mode == 1) v = (((const float*)mraw)[i] != 0.0f);
        else                v = (((const unsigned char*)mraw)[i] != 0);
        g_mask[i] = v;
    }
}

// ---------------- kernel 1: x = inp @ W + b  (64x1024, K=512) ----------------
__global__ __launch_bounds__(256) void xgemm_kernel(const float* __restrict__ inp,
                                                    const float* __restrict__ Wm,
                                                    const float* __restrict__ bias) {
    __shared__ float ws[DIN * 8];
    int h0 = blockIdx.x * 8;
    int t  = threadIdx.x;
    for (int idx = t; idx < DIN * 8; idx += 256) {
        int k = idx >> 3, j = idx & 7;
        ws[idx] = Wm[k * HH + h0 + j];
    }
    __syncthreads();

    int b  = t >> 2;
    int j0 = (t & 3) * 2;
    float acc0 = bias[h0 + j0];
    float acc1 = bias[h0 + j0 + 1];
    const float4* ip = (const float4*)(inp + b * DIN);
#pragma unroll 4
    for (int k4 = 0; k4 < DIN / 4; k4++) {
        float4 p = __ldg(&ip[k4]);
        int kb = k4 * 32 + j0;
        float2 w0 = *(const float2*)&ws[kb];
        float2 w1 = *(const float2*)&ws[kb + 8];
        float2 w2 = *(const float2*)&ws[kb + 16];
        float2 w3 = *(const float2*)&ws[kb + 24];
        acc0 = fmaf(p.x, w0.x, acc0); acc1 = fmaf(p.x, w0.y, acc1);
        acc0 = fmaf(p.y, w1.x, acc0); acc1 = fmaf(p.y, w1.y, acc1);
        acc0 = fmaf(p.z, w2.x, acc0); acc1 = fmaf(p.z, w2.y, acc1);
        acc0 = fmaf(p.w, w3.x, acc0); acc1 = fmaf(p.w, w3.y, acc1);
    }
    g_x[b * HH + h0 + j0]     = acc0;
    g_x[b * HH + h0 + j0 + 1] = acc1;
}

// ---------------- kernel 2: fused scores + exp-sum + weighted sum -----------
// Persistent CTAs of 512 threads (16 warps, 4/SMSP for latency hiding).
// Warp pair (2g, 2g+1) co-owns a 16-row group: each warp handles 512 of the
// 1024 H-elements (80 regs of state/lane instead of 160). Per-row score halves
// are exchanged via a double-buffered smem mailbox + named barrier.
__device__ __forceinline__ void loadrow4(float4 (&c)[4], const float* cbase,
                                         int s, int ln) {
    const float4* crow = (const float4*)(cbase + (size_t)s * HH);
#pragma unroll
    for (int g = 0; g < 4; g++) c[g] = __ldg(&crow[g * 32 + ln]);
}

__global__ __launch_bounds__(512, 1) void pass1_kernel(const float* __restrict__ ctx,
                                                       const float* __restrict__ v) {
    __shared__ float    s_acc[16][512];   // 32 KB
    __shared__ float    s_part[2][8][2];  // [parity][rowgrp][half]
    __shared__ float    s_l[8];
    __shared__ unsigned s_tile;

    int t      = threadIdx.x;
    int w      = t >> 5;        // 0..15
    int ln     = t & 31;
    int rowgrp = w >> 1;        // 0..7
    int half   = w & 1;         // H half this warp owns

    float4 vv[4];
    const float4* vr = (const float4*)v + half * 128;
#pragma unroll
    for (int g = 0; g < 4; g++) vv[g] = vr[g * 32 + ln];

    while (true) {
        if (t == 0) s_tile = atomicAdd(&g_ticket, 1u);
        __syncthreads();
        unsigned tile = s_tile;
        if (tile >= NTILES) break;

        int b  = tile >> 4;          // SPLITS = 16
        int sp = tile & (SPLITS - 1);

        float4 xv[4], acc[4];
        const float4* xr = (const float4*)(g_x + b * HH) + half * 128;
#pragma unroll
        for (int g = 0; g < 4; g++) {
            xv[g]  = xr[g * 32 + ln];
            acc[g] = make_float4(0.f, 0.f, 0.f, 0.f);
        }
        float l = 0.f;

        int gsrow = b * SS + sp * ROWS_PER_TILE + rowgrp * ROWS_PER_GRP;
        unsigned char mk = (ln < ROWS_PER_GRP) ? g_mask[gsrow + ln] : 1;
        unsigned bits = __ballot_sync(0xffffffffu, mk == 0);
        if (half == 0 && ln < ROWS_PER_GRP && mk) g_score[gsrow + ln] = NEG_INF;

        const float* cbase = ctx + (size_t)gsrow * HH + half * 512;
        unsigned rem = bits;
        int parity = 0;
        if (rem) {
            int s_cur = __ffs((int)rem) - 1; rem &= rem - 1;
            float4 cc[4];
            loadrow4(cc, cbase, s_cur, ln);
            while (true) {
                int s_nxt = -1;
                float4 cn[4];
                if (rem) {                       // prefetch next unmasked row
                    s_nxt = __ffs((int)rem) - 1; rem &= rem - 1;
                    loadrow4(cn, cbase, s_nxt, ln);
                }
                float part = 0.f;
#pragma unroll
                for (int g = 0; g < 4; g++) {
                    float4 a = xv[g], c = cc[g], vg = vv[g];
                    part = fmaf(tanh_acc(a.x + c.x), vg.x, part);
                    part = fmaf(tanh_acc(a.y + c.y), vg.y, part);
                    part = fmaf(tanh_acc(a.z + c.z), vg.z, part);
                    part = fmaf(tanh_acc(a.w + c.w), vg.w, part);
                }
#pragma unroll
                for (int off = 16; off; off >>= 1)
                    part += __shfl_xor_sync(0xffffffffu, part, off);

                if (ln == 0) s_part[parity][rowgrp][half] = part;
                asm volatile("bar.sync %0, %1;" :: "r"(rowgrp + 1), "n"(64) : "memory");
                float score = s_part[parity][rowgrp][0] + s_part[parity][rowgrp][1];

                if (half == 0 && ln == 0) g_score[gsrow + s_cur] = score;
                float p = __expf(score);         // fixed reference M=0: |score|<40
                l += p;
#pragma unroll
                for (int g = 0; g < 4; g++) {
                    acc[g].x = fmaf(cc[g].x, p, acc[g].x);
                    acc[g].y = fmaf(cc[g].y, p, acc[g].y);
                    acc[g].z = fmaf(cc[g].z, p, acc[g].z);
                    acc[g].w = fmaf(cc[g].w, p, acc[g].w);
                }
                if (s_nxt < 0) break;
#pragma unroll
                for (int g = 0; g < 4; g++) cc[g] = cn[g];
                s_cur = s_nxt;
                parity ^= 1;
            }
        }

        // ---- combine 16 warps within CTA ----
#pragma unroll
        for (int g = 0; g < 4; g++)
            *(float4*)&s_acc[w][g * 128 + ln * 4] = acc[g];
        if (half == 0 && ln == 0) s_l[rowgrp] = l;
        __syncthreads();

        if (t < 256) {                 // 256 float4 = 1024 floats of output
            int hhalf = t >> 7;
            int loc   = (t & 127) * 4;
            float4 sum = make_float4(0.f, 0.f, 0.f, 0.f);
#pragma unroll
            for (int rg = 0; rg < 8; rg++) {
                float4 a = *(const float4*)&s_acc[rg * 2 + hhalf][loc];
                sum.x += a.x; sum.y += a.y; sum.z += a.z; sum.w += a.w;
            }
            *(float4*)&g_acc[(size_t)tile * HH + t * 4] = sum;
        } else if (t == 256) {
            float L = 0.f;
#pragma unroll
            for (int rg = 0; rg < 8; rg++) L += s_l[rg];
            g_l[tile] = L;
        }
        __syncthreads();   // protect s_acc/s_l/s_tile before next tile
    }
}

// ---------------- kernel 3: merge tiles, emit attn_applied + attn_weights ---
// grid = 64*16 CTAs x 128 threads: high CTA count to beat latency.
__global__ __launch_bounds__(128) void combine_kernel(float* __restrict__ out_applied,
                                                      float* __restrict__ out_w) {
    int b    = blockIdx.x >> 4;
    int part = blockIdx.x & 15;
    int t    = threadIdx.x;

    float L = 0.f;
#pragma unroll
    for (int i = 0; i < SPLITS; i++) L += g_l[b * SPLITS + i];
    float invL = 1.0f / L;

    if (t < 64) {
        int h = part * 64 + t;
        float s = 0.f;
#pragma unroll
        for (int i = 0; i < SPLITS; i++)
            s += g_acc[(size_t)(b * SPLITS + i) * HH + h];
        out_applied[b * HH + h] = s * invL;
    }
    int s_idx = part * 128 + t;
    float sc = g_score[b * SS + s_idx];            // -inf on masked -> exact 0
    out_w[b * SS + s_idx] = __expf(sc) * invL;
}

// ---------------- launch ----------------
extern "C" void kernel_launch(void* const* d_in, const int* in_sizes, int n_in,
                              void* d_out, int out_size) {
    const float* inp  = (const float*)d_in[0];
    // d_in[1] = hidden (unused by the reference computation)
    const float* ctx  = (const float*)d_in[2];
    const void*  mask = d_in[3];
    const float* Wm   = (const float*)d_in[4];
    const float* bias = (const float*)d_in[5];
    const float* v    = (const float*)d_in[6];
    float* out = (float*)d_out;

    mask_norm_kernel<<<128, 256>>>(mask);
    xgemm_kernel<<<128, 256>>>(inp, Wm, bias);
    pass1_kernel<<<152, 512>>>(ctx, v);
    combine_kernel<<<BB * 16, 128>>>(out, out + BB * HH);
}

// round 4
// speedup vs baseline: 1.4919x; 1.2256x over previous
#include <cuda_runtime.h>
#include <cstdint>
#include <cstddef>

#define BB 64
#define SS 2048
#define DIN 512
#define HH 1024
#define SPLITS 16                      // tiles per batch; 1024 tiles total
#define NTILES (BB * SPLITS)
#define ROWS_PER_TILE (SS / SPLITS)    // 128
#define NWARP 16
#define RING_DEPTH 2

#define NEG_INF __int_as_float(0xff800000)

// ---------------- scratch (no allocations allowed) ----------------
__device__ float          g_x[BB * HH];                 // inp@W + b
__device__ unsigned char  g_mask[BB * SS];              // canonical mask (1 = masked)
__device__ float          g_score[BB * SS];             // raw scores (-inf where masked)
__device__ float          g_acc[NTILES * HH];           // tile partial weighted sums
__device__ float          g_l[NTILES];                  // tile partial sum-of-exp
__device__ unsigned       g_ticket;                     // persistent work queue

// ---------------- helpers ----------------
__device__ __forceinline__ float tanh_acc(float x) {
    // tanh(x) = 1 - 2/(exp(2x)+1); __expf+__fdividef = 2 MUFU, abs err ~1e-7
    float e = __expf(2.0f * x);
    return 1.0f - __fdividef(2.0f, e + 1.0f);
}

// ---------------- kernel 0 (fused prologue) --------------------------------
// blocks [0,128):   x = inp @ W + b   (64x1024, K=512)
// blocks [128,192): mask canonicalize + ticket reset
__global__ __launch_bounds__(256) void prologue_kernel(const float* __restrict__ inp,
                                                       const float* __restrict__ Wm,
                                                       const float* __restrict__ bias,
                                                       const void*  __restrict__ mraw) {
    __shared__ float ws[DIN * 8];
    int t   = threadIdx.x;
    int blk = blockIdx.x;

    if (blk < 128) {                               // ---- xgemm part ----
        int h0 = blk * 8;
        for (int idx = t; idx < DIN * 8; idx += 256) {
            int k = idx >> 3, j = idx & 7;
            ws[idx] = Wm[k * HH + h0 + j];
        }
        __syncthreads();

        int b  = t >> 2;
        int j0 = (t & 3) * 2;
        float acc0 = bias[h0 + j0];
        float acc1 = bias[h0 + j0 + 1];
        const float4* ip = (const float4*)(inp + b * DIN);
#pragma unroll 4
        for (int k4 = 0; k4 < DIN / 4; k4++) {
            float4 p = __ldg(&ip[k4]);
            int kb = k4 * 32 + j0;
            float2 w0 = *(const float2*)&ws[kb];
            float2 w1 = *(const float2*)&ws[kb + 8];
            float2 w2 = *(const float2*)&ws[kb + 16];
            float2 w3 = *(const float2*)&ws[kb + 24];
            acc0 = fmaf(p.x, w0.x, acc0); acc1 = fmaf(p.x, w0.y, acc1);
            acc0 = fmaf(p.y, w1.x, acc0); acc1 = fmaf(p.y, w1.y, acc1);
            acc0 = fmaf(p.z, w2.x, acc0); acc1 = fmaf(p.z, w2.y, acc1);
            acc0 = fmaf(p.w, w3.x, acc0); acc1 = fmaf(p.w, w3.y, acc1);
        }
        g_x[b * HH + h0 + j0]     = acc0;
        g_x[b * HH + h0 + j0 + 1] = acc1;
    } else {                                       // ---- mask part ----
        if (blk == 128 && t == 0) g_ticket = 0;
        const unsigned* wds = (const unsigned*)mraw;
        int notInt = 0, notFloat = 0;
        for (int i = t; i < 1024; i += 256) {
            unsigned x = wds[i];
            notInt   |= (x > 1u);
            notFloat |= (x != 0u && x != 0x3F800000u);
        }
        notInt   = __syncthreads_or(notInt);
        notFloat = __syncthreads_or(notFloat);
        int mode = notInt ? (notFloat ? 2 : 1) : 0;   // 0:int32 1:float32 2:bytes

        int base = (blk - 128) * 2048;
        for (int i = base + t; i < base + 2048; i += 256) {
            unsigned char v;
            if (mode == 0)      v = (((const int*)mraw)[i] != 0);
            else if (mode == 1) v = (((const float*)mraw)[i] != 0.0f);
            else                v = (((const unsigned char*)mraw)[i] != 0);
            g_mask[i] = v;
        }
    }
}

// ---------------- kernel 1: fused scores + exp-sum + weighted sum -----------
// Persistent CTAs of 512 threads. Warp owns full 4KB rows, dealt round-robin
// from a per-tile compacted unmasked-row list. Rows staged through a per-warp
// cp.async smem ring (depth 2) -> zero register cost for prefetch, high MLP.
__device__ __forceinline__ void issue_row(const float* cb, int k, int n,
                                          unsigned slot_u32, int ln,
                                          const int* s_idx) {
    if (k < n) {
        const float* src = cb + (size_t)s_idx[k] * HH + ln * 4;
        unsigned dst = slot_u32 + ln * 16;
#pragma unroll
        for (int i = 0; i < 8; i++)
            asm volatile("cp.async.cg.shared.global [%0], [%1], 16;"
                         :: "r"(dst + i * 512), "l"(src + i * 128) : "memory");
    }
    asm volatile("cp.async.commit_group;" ::: "memory");
}

__global__ __launch_bounds__(512, 1) void pass1_kernel(const float* __restrict__ ctx,
                                                       const float* __restrict__ v) {
    extern __shared__ float dsm[];
    float* xs   = dsm;                 // HH floats
    float* ring = dsm + HH;            // NWARP * RING_DEPTH * HH floats

    __shared__ int      s_idx[ROWS_PER_TILE];
    __shared__ int      s_wcnt[4];
    __shared__ float    s_l[NWARP];
    __shared__ unsigned s_tile;

    int t  = threadIdx.x;
    int w  = t >> 5;
    int ln = t & 31;

    float4 vv[8];
    const float4* vr = (const float4*)v;
#pragma unroll
    for (int j = 0; j < 8; j++) vv[j] = __ldg(&vr[j * 32 + ln]);

    float* myring = ring + w * (RING_DEPTH * HH);
    unsigned ring_u32 = (unsigned)__cvta_generic_to_shared(myring);

    for (;;) {
        if (t == 0) s_tile = atomicAdd(&g_ticket, 1u);
        __syncthreads();               // also orders prior tile's smem reuse
        unsigned tile = s_tile;
        if (tile >= NTILES) break;

        int b  = tile >> 4;            // SPLITS = 16
        int sp = tile & (SPLITS - 1);
        int rowbase = b * SS + sp * ROWS_PER_TILE;

        xs[t]       = g_x[b * HH + t];
        xs[t + 512] = g_x[b * HH + 512 + t];

        // ---- compact unmasked row indices (deterministic order) ----
        unsigned char mk = 1;
        if (t < ROWS_PER_TILE) mk = g_mask[rowbase + t];
        unsigned bits = __ballot_sync(0xffffffffu, mk == 0);
        if (t < ROWS_PER_TILE && mk) g_score[rowbase + t] = NEG_INF;
        if (w < 4 && ln == 0) s_wcnt[w] = __popc(bits);
        __syncthreads();
        int n = s_wcnt[0] + s_wcnt[1] + s_wcnt[2] + s_wcnt[3];
        if (t < ROWS_PER_TILE && !mk) {
            int basew = 0;
#pragma unroll
            for (int i = 0; i < 4; i++) if (i < w) basew += s_wcnt[i];
            s_idx[basew + __popc(bits & ((1u << ln) - 1u))] = t;
        }
        __syncthreads();

        // ---- per-warp row loop over compacted list ----
        float4 acc[8];
#pragma unroll
        for (int j = 0; j < 8; j++) acc[j] = make_float4(0.f, 0.f, 0.f, 0.f);
        float l = 0.f;

        const float* cb = ctx + (size_t)rowbase * HH;
        issue_row(cb, w,      n, ring_u32,          ln, s_idx);
        issue_row(cb, w + 16, n, ring_u32 + HH * 4, ln, s_idx);
        int slot = 0;
        for (int k = w; k < n; k += NWARP) {
            asm volatile("cp.async.wait_group 1;" ::: "memory");
            __syncwarp();
            const float* sp_ = myring + slot * HH;

            float4 cc[8];
            float part = 0.f;
#pragma unroll
            for (int j = 0; j < 8; j++) {
                cc[j] = *(const float4*)&sp_[j * 128 + ln * 4];
                float4 xj = *(const float4*)&xs[j * 128 + ln * 4];
                float4 vg = vv[j];
                part = fmaf(tanh_acc(xj.x + cc[j].x), vg.x, part);
                part = fmaf(tanh_acc(xj.y + cc[j].y), vg.y, part);
                part = fmaf(tanh_acc(xj.z + cc[j].z), vg.z, part);
                part = fmaf(tanh_acc(xj.w + cc[j].w), vg.w, part);
            }
#pragma unroll
            for (int off = 16; off; off >>= 1)
                part += __shfl_xor_sync(0xffffffffu, part, off);

            if (ln == 0) g_score[rowbase + s_idx[k]] = part;
            float p = __expf(part);    // fixed reference M=0: |score| < 40
            l += p;
#pragma unroll
            for (int j = 0; j < 8; j++) {
                acc[j].x = fmaf(cc[j].x, p, acc[j].x);
                acc[j].y = fmaf(cc[j].y, p, acc[j].y);
                acc[j].z = fmaf(cc[j].z, p, acc[j].z);
                acc[j].w = fmaf(cc[j].w, p, acc[j].w);
            }
            issue_row(cb, k + 2 * NWARP, n, ring_u32 + slot * HH * 4, ln, s_idx);
            slot ^= 1;
        }
        asm volatile("cp.async.wait_group 0;" ::: "memory");

        // ---- CTA combine: overlay acc onto ring smem, tree-reduce ----
        if (ln == 0) s_l[w] = l;
        __syncthreads();               // everyone done with their ring slots
        float* sout = ring;            // 16*HH floats overlay (ring is 32*HH)
#pragma unroll
        for (int j = 0; j < 8; j++)
            *(float4*)&sout[w * HH + j * 128 + ln * 4] = acc[j];
        __syncthreads();

        float L = 0.f;
#pragma unroll
        for (int i = 0; i < NWARP; i++) L += s_l[i];
        float sum0 = 0.f, sum1 = 0.f;
#pragma unroll
        for (int i = 0; i < NWARP; i++) {
            sum0 += sout[i * HH + t];
            sum1 += sout[i * HH + t + 512];
        }
        g_acc[(size_t)tile * HH + t]       = sum0;
        g_acc[(size_t)tile * HH + t + 512] = sum1;
        if (t == 0) g_l[tile] = L;
        // top-of-loop __syncthreads orders smem reuse for the next tile
    }
}

// ---------------- kernel 2: merge tiles, emit outputs -----------------------
__global__ __launch_bounds__(256) void combine_kernel(float* __restrict__ out_applied,
                                                      float* __restrict__ out_w) {
    int b    = blockIdx.x >> 3;
    int part = blockIdx.x & 7;
    int t    = threadIdx.x;

    float L = 0.f;
#pragma unroll
    for (int i = 0; i < SPLITS; i++) L += g_l[b * SPLITS + i];
    float invL = 1.0f / L;

    if (t < 128) {
        int h = part * 128 + t;
        float s = 0.f;
#pragma unroll
        for (int i = 0; i < SPLITS; i++)
            s += g_acc[(size_t)(b * SPLITS + i) * HH + h];
        out_applied[b * HH + h] = s * invL;
    }
    int si = part * 256 + t;
    float sc = g_score[b * SS + si];               // -inf on masked -> exact 0
    out_w[b * SS + si] = __expf(sc) * invL;
}

// ---------------- launch ----------------
extern "C" void kernel_launch(void* const* d_in, const int* in_sizes, int n_in,
                              void* d_out, int out_size) {
    const float* inp  = (const float*)d_in[0];
    // d_in[1] = hidden (unused by the reference computation)
    const float* ctx  = (const float*)d_in[2];
    const void*  mask = d_in[3];
    const float* Wm   = (const float*)d_in[4];
    const float* bias = (const float*)d_in[5];
    const float* v    = (const float*)d_in[6];
    float* out = (float*)d_out;

    const int dyn_smem = (HH + NWARP * RING_DEPTH * HH) * (int)sizeof(float);
    cudaFuncSetAttribute(pass1_kernel,
                         cudaFuncAttributeMaxDynamicSharedMemorySize, dyn_smem);

    prologue_kernel<<<192, 256>>>(inp, Wm, bias, mask);
    pass1_kernel<<<152, 512, dyn_smem>>>(ctx, v);
    combine_kernel<<<BB * 8, 256>>>(out, out + BB * HH);
}

// round 5
// speedup vs baseline: 1.7887x; 1.1990x over previous
#include <cuda_runtime.h>
#include <cstdint>
#include <cstddef>

#define BB 64
#define SS 2048
#define DIN 512
#define HH 1024
#define SPLITS 8                       // tiles per batch; 512 tiles total
#define NTILES (BB * SPLITS)
#define ROWS_PER_TILE (SS / SPLITS)    // 256
#define NWARP 16
#define RING_DEPTH 3
#define KSPLIT 8                       // gemm k-chunks
#define KC 64
#define HC 64

#define NEG_INF __int_as_float(0xff800000)

// ---------------- scratch (no allocations allowed) ----------------
__device__ __align__(16) float g_x[BB * HH];            // inp@W + b
__device__ __align__(16) float g_xpart[KSPLIT * BB * HH];
__device__ unsigned char  g_mask[BB * SS];              // canonical mask (1 = masked)
__device__ float          g_score[BB * SS];             // raw scores (-inf where masked)
__device__ __align__(16) float g_acc[NTILES * HH];      // tile partial weighted sums
__device__ float          g_l[NTILES];                  // tile partial sum-of-exp
__device__ unsigned       g_ticket;                     // persistent work queue

// ---------------- helpers ----------------
__device__ __forceinline__ float tanh_acc(float x) {
    // tanh(x) = 1 - 2/(exp(2x)+1); __expf+__fdividef = 2 MUFU, abs err ~1e-7
    float e = __expf(2.0f * x);
    return 1.0f - __fdividef(2.0f, e + 1.0f);
}

// ---------------- kernel 0: gemm partials (reg-tiled) + mask canon ----------
// blocks [0,128):  partial x = inp[:, k-chunk] @ W[k-chunk, h-chunk]
// blocks [128,192): mask canonicalize
__global__ __launch_bounds__(256) void prologue_kernel(const float* __restrict__ inp,
                                                       const float* __restrict__ Wm,
                                                       const void*  __restrict__ mraw) {
    __shared__ float Ws[KC][HC];   // 16 KB
    __shared__ float Is[KC][BB];   // 16 KB (k-major: per-k batch row contiguous)
    int t   = threadIdx.x;
    int blk = blockIdx.x;

    if (blk < 128) {
        int kc = blk >> 4, hcb = blk & 15;
        int k0 = kc * KC, h0 = hcb * HC;

        // W slab: 64x64, coalesced float4
        for (int i = t; i < KC * HC / 4; i += 256) {
            int k = i >> 4, hj = i & 15;
            *(float4*)&Ws[k][hj * 4] =
                *(const float4*)&Wm[(size_t)(k0 + k) * HH + h0 + hj * 4];
        }
        // inp slab transposed: Is[k][b] = inp[b][k0+k]
        for (int i = t; i < BB * KC / 4; i += 256) {
            int b = i & 63, j = i >> 6;
            float4 p = *(const float4*)&inp[b * DIN + k0 + j * 4];
            Is[j * 4 + 0][b] = p.x;
            Is[j * 4 + 1][b] = p.y;
            Is[j * 4 + 2][b] = p.z;
            Is[j * 4 + 3][b] = p.w;
        }
        __syncthreads();

        int ty = t >> 4, tx = t & 15;           // 4 batches x 4 cols per thread
        float4 a0 = {0,0,0,0}, a1 = {0,0,0,0}, a2 = {0,0,0,0}, a3 = {0,0,0,0};
#pragma unroll 8
        for (int k = 0; k < KC; k++) {
            float4 ib = *(const float4*)&Is[k][ty * 4];
            float4 wv = *(const float4*)&Ws[k][tx * 4];
            a0.x = fmaf(ib.x, wv.x, a0.x); a0.y = fmaf(ib.x, wv.y, a0.y);
            a0.z = fmaf(ib.x, wv.z, a0.z); a0.w = fmaf(ib.x, wv.w, a0.w);
            a1.x = fmaf(ib.y, wv.x, a1.x); a1.y = fmaf(ib.y, wv.y, a1.y);
            a1.z = fmaf(ib.y, wv.z, a1.z); a1.w = fmaf(ib.y, wv.w, a1.w);
            a2.x = fmaf(ib.z, wv.x, a2.x); a2.y = fmaf(ib.z, wv.y, a2.y);
            a2.z = fmaf(ib.z, wv.z, a2.z); a2.w = fmaf(ib.z, wv.w, a2.w);
            a3.x = fmaf(ib.w, wv.x, a3.x); a3.y = fmaf(ib.w, wv.y, a3.y);
            a3.z = fmaf(ib.w, wv.z, a3.z); a3.w = fmaf(ib.w, wv.w, a3.w);
        }
        float* outb = g_xpart + (size_t)kc * (BB * HH) + h0 + tx * 4;
        *(float4*)&outb[(ty * 4 + 0) * HH] = a0;
        *(float4*)&outb[(ty * 4 + 1) * HH] = a1;
        *(float4*)&outb[(ty * 4 + 2) * HH] = a2;
        *(float4*)&outb[(ty * 4 + 3) * HH] = a3;
    } else {                                    // ---- mask canonicalize ----
        const unsigned* wds = (const unsigned*)mraw;
        int notInt = 0, notFloat = 0;
        for (int i = t; i < 1024; i += 256) {
            unsigned x = wds[i];
            notInt   |= (x > 1u);
            notFloat |= (x != 0u && x != 0x3F800000u);
        }
        notInt   = __syncthreads_or(notInt);
        notFloat = __syncthreads_or(notFloat);
        int mode = notInt ? (notFloat ? 2 : 1) : 0;  // 0:int32 1:float32 2:bytes

        int base = (blk - 128) * 2048;
        for (int i = base + t; i < base + 2048; i += 256) {
            unsigned char v;
            if (mode == 0)      v = (((const int*)mraw)[i] != 0);
            else if (mode == 1) v = (((const float*)mraw)[i] != 0.0f);
            else                v = (((const unsigned char*)mraw)[i] != 0);
            g_mask[i] = v;
        }
    }
}

// ---------------- kernel 1: reduce gemm partials + bias, reset ticket -------
__global__ __launch_bounds__(256) void xreduce_kernel(const float* __restrict__ bias) {
    int i = blockIdx.x * 256 + threadIdx.x;     // float4 index, 16384 total
    if (i == 0) g_ticket = 0;
    float4 s = *(const float4*)&bias[(i & 255) * 4];
    const float4* xp = (const float4*)g_xpart;
#pragma unroll
    for (int kc = 0; kc < KSPLIT; kc++) {
        float4 p = xp[kc * (BB * HH / 4) + i];
        s.x += p.x; s.y += p.y; s.z += p.z; s.w += p.w;
    }
    ((float4*)g_x)[i] = s;
}

// ---------------- kernel 2: fused scores + exp-sum + weighted sum -----------
// Persistent CTAs of 512 threads. Warp owns full 4KB rows dealt round-robin
// from a compacted unmasked-row list; rows staged through a per-warp cp.async
// ring (depth 3 -> 2 rows in flight per warp, zero register cost).
__device__ __forceinline__ void issue_row(const float* cb, int k, int n,
                                          unsigned slot_u32, int ln,
                                          const int* s_idx) {
    if (k < n) {
        const float* src = cb + (size_t)s_idx[k] * HH + ln * 4;
        unsigned dst = slot_u32 + ln * 16;
#pragma unroll
        for (int i = 0; i < 8; i++)
            asm volatile("cp.async.cg.shared.global [%0], [%1], 16;"
                         :: "r"(dst + i * 512), "l"(src + i * 128) : "memory");
    }
    asm volatile("cp.async.commit_group;" ::: "memory");
}

__global__ __launch_bounds__(512, 1) void pass1_kernel(const float* __restrict__ ctx,
                                                       const float* __restrict__ v) {
    extern __shared__ float dsm[];
    float* xs   = dsm;                 // HH floats
    float* ring = dsm + HH;            // NWARP * RING_DEPTH * HH floats (192KB)

    __shared__ int      s_idx[ROWS_PER_TILE];
    __shared__ int      s_wcnt[8];
    __shared__ float    s_l[NWARP];
    __shared__ unsigned s_tile;

    int t  = threadIdx.x;
    int w  = t >> 5;
    int ln = t & 31;

    float4 vv[8];
    const float4* vr = (const float4*)v;
#pragma unroll
    for (int j = 0; j < 8; j++) vv[j] = __ldg(&vr[j * 32 + ln]);

    float* myring = ring + w * (RING_DEPTH * HH);
    unsigned ring_u32 = (unsigned)__cvta_generic_to_shared(myring);

    for (;;) {
        if (t == 0) s_tile = atomicAdd(&g_ticket, 1u);
        __syncthreads();               // also orders prior tile's smem reuse
        unsigned tile = s_tile;
        if (tile >= NTILES) break;

        int b  = tile >> 3;            // SPLITS = 8
        int sp = tile & (SPLITS - 1);
        int rowbase = b * SS + sp * ROWS_PER_TILE;

        xs[t]       = g_x[b * HH + t];
        xs[t + 512] = g_x[b * HH + 512 + t];

        // ---- compact unmasked row indices (deterministic order) ----
        unsigned char mk = 1;
        if (t < ROWS_PER_TILE) mk = g_mask[rowbase + t];
        unsigned bits = __ballot_sync(0xffffffffu, mk == 0);
        if (t < ROWS_PER_TILE && mk) g_score[rowbase + t] = NEG_INF;
        if (w < 8 && ln == 0) s_wcnt[w] = __popc(bits);
        __syncthreads();
        int n = 0;
#pragma unroll
        for (int i = 0; i < 8; i++) n += s_wcnt[i];
        if (t < ROWS_PER_TILE && !mk) {
            int basew = 0;
#pragma unroll
            for (int i = 0; i < 8; i++) if (i < w) basew += s_wcnt[i];
            s_idx[basew + __popc(bits & ((1u << ln) - 1u))] = t;
        }
        __syncthreads();

        // ---- per-warp row loop over compacted list ----
        float4 acc[8];
#pragma unroll
        for (int j = 0; j < 8; j++) acc[j] = make_float4(0.f, 0.f, 0.f, 0.f);
        float l = 0.f;

        const float* cb = ctx + (size_t)rowbase * HH;
        issue_row(cb, w,             n, ring_u32,              ln, s_idx);
        issue_row(cb, w + NWARP,     n, ring_u32 + HH * 4,     ln, s_idx);
        issue_row(cb, w + 2 * NWARP, n, ring_u32 + HH * 8,     ln, s_idx);
        int slot = 0;
        for (int k = w; k < n; k += NWARP) {
            asm volatile("cp.async.wait_group 2;" ::: "memory");
            const float* sp_ = myring + slot * HH;   // this thread's own bytes

            float part = 0.f;
#pragma unroll
            for (int j = 0; j < 8; j++) {
                float4 c  = *(const float4*)&sp_[j * 128 + ln * 4];
                float4 xj = *(const float4*)&xs[j * 128 + ln * 4];
                float4 vg = vv[j];
                part = fmaf(tanh_acc(xj.x + c.x), vg.x, part);
                part = fmaf(tanh_acc(xj.y + c.y), vg.y, part);
                part = fmaf(tanh_acc(xj.z + c.z), vg.z, part);
                part = fmaf(tanh_acc(xj.w + c.w), vg.w, part);
            }
#pragma unroll
            for (int off = 16; off; off >>= 1)
                part += __shfl_xor_sync(0xffffffffu, part, off);

            if (ln == 0) g_score[rowbase + s_idx[k]] = part;
            float p = __expf(part);    // fixed reference M=0: |score| < 40
            l += p;
#pragma unroll
            for (int j = 0; j < 8; j++) {          // re-read row (LDS cheap)
                float4 c = *(const float4*)&sp_[j * 128 + ln * 4];
                acc[j].x = fmaf(c.x, p, acc[j].x);
                acc[j].y = fmaf(c.y, p, acc[j].y);
                acc[j].z = fmaf(c.z, p, acc[j].z);
                acc[j].w = fmaf(c.w, p, acc[j].w);
            }
            issue_row(cb, k + 3 * NWARP, n, ring_u32 + slot * HH * 4, ln, s_idx);
            slot = (slot == RING_DEPTH - 1) ? 0 : slot + 1;
        }
        asm volatile("cp.async.wait_group 0;" ::: "memory");

        // ---- CTA combine: overlay acc onto ring smem, tree-reduce ----
        if (ln == 0) s_l[w] = l;
        __syncthreads();               // everyone done with their ring slots
        float* sout = ring;            // 16*HH floats overlay
#pragma unroll
        for (int j = 0; j < 8; j++)
            *(float4*)&sout[w * HH + j * 128 + ln * 4] = acc[j];
        __syncthreads();

        float L = 0.f;
#pragma unroll
        for (int i = 0; i < NWARP; i++) L += s_l[i];
        float sum0 = 0.f, sum1 = 0.f;
#pragma unroll
        for (int i = 0; i < NWARP; i++) {
            sum0 += sout[i * HH + t];
            sum1 += sout[i * HH + t + 512];
        }
        g_acc[(size_t)tile * HH + t]       = sum0;
        g_acc[(size_t)tile * HH + t + 512] = sum1;
        if (t == 0) g_l[tile] = L;
        // top-of-loop __syncthreads orders smem reuse for the next tile
    }
}

// ---------------- kernel 3: merge tiles, emit outputs -----------------------
__global__ __launch_bounds__(256) void combine_kernel(float* __restrict__ out_applied,
                                                      float* __restrict__ out_w) {
    int b    = blockIdx.x >> 3;
    int part = blockIdx.x & 7;
    int t    = threadIdx.x;

    float L = 0.f;
#pragma unroll
    for (int i = 0; i < SPLITS; i++) L += g_l[b * SPLITS + i];
    float invL = 1.0f / L;

    if (t < 128) {
        int h = part * 128 + t;
        float s = 0.f;
#pragma unroll
        for (int i = 0; i < SPLITS; i++)
            s += g_acc[(size_t)(b * SPLITS + i) * HH + h];
        out_applied[b * HH + h] = s * invL;
    }
    int si = part * 256 + t;
    float sc = g_score[b * SS + si];               // -inf on masked -> exact 0
    out_w[b * SS + si] = __expf(sc) * invL;
}

// ---------------- launch ----------------
extern "C" void kernel_launch(void* const* d_in, const int* in_sizes, int n_in,
                              void* d_out, int out_size) {
    const float* inp  = (const float*)d_in[0];
    // d_in[1] = hidden (unused by the reference computation)
    const float* ctx  = (const float*)d_in[2];
    const void*  mask = d_in[3];
    const float* Wm   = (const float*)d_in[4];
    const float* bias = (const float*)d_in[5];
    const float* v    = (const float*)d_in[6];
    float* out = (float*)d_out;

    const int dyn_smem = (HH + NWARP * RING_DEPTH * HH) * (int)sizeof(float);
    cudaFuncSetAttribute(pass1_kernel,
                         cudaFuncAttributeMaxDynamicSharedMemorySize, dyn_smem);

    prologue_kernel<<<192, 256>>>(inp, Wm, mask);
    xreduce_kernel<<<BB * HH / 1024, 256>>>(bias);
    pass1_kernel<<<152, 512, dyn_smem>>>(ctx, v);
    combine_kernel<<<BB * 8, 256>>>(out, out + BB * HH);
}

// round 6
// speedup vs baseline: 1.8282x; 1.0221x over previous
#include <cuda_runtime.h>
#include <cstdint>
#include <cstddef>

#define BB 64
#define SS 2048
#define DIN 512
#define HH 1024
#define SPLITS 8                       // tiles per batch; 512 tiles total
#define NTILES (BB * SPLITS)
#define ROWS_PER_TILE (SS / SPLITS)    // 256
#define NWARP 16
#define RING_DEPTH 3
#define KSPLIT 8                       // gemm k-chunks
#define KC 64
#define HC 64

#define NEG_INF __int_as_float(0xff800000)

// ---------------- scratch (no allocations allowed) ----------------
__device__ __align__(16) float g_x[BB * HH];            // inp@W + b
__device__ __align__(16) float g_xpart[KSPLIT * BB * HH];
__device__ unsigned char  g_mask[BB * SS];              // canonical mask (1 = masked)
__device__ float          g_score[BB * SS];             // raw scores (-inf where masked)
__device__ __align__(16) float g_acc[NTILES * HH];      // tile partial weighted sums
__device__ float          g_l[NTILES];                  // tile partial sum-of-exp
__device__ unsigned       g_ticket;                     // persistent work queue
__device__ unsigned       g_bdone[BB];                  // per-batch tile completion

// ---------------- helpers ----------------
__device__ __forceinline__ float tanh_fast(float x) {
    float y;
    asm("tanh.approx.f32 %0, %1;" : "=f"(y) : "f"(x));
    return y;
}

// ---------------- kernel 0: gemm partials (reg-tiled) + mask canon ----------
__global__ __launch_bounds__(256) void prologue_kernel(const float* __restrict__ inp,
                                                       const float* __restrict__ Wm,
                                                       const void*  __restrict__ mraw) {
    __shared__ float Ws[KC][HC];   // 16 KB
    __shared__ float Is[KC][BB];   // 16 KB (k-major)
    int t   = threadIdx.x;
    int blk = blockIdx.x;

    if (blk < 128) {
        int kc = blk >> 4, hcb = blk & 15;
        int k0 = kc * KC, h0 = hcb * HC;

        for (int i = t; i < KC * HC / 4; i += 256) {
            int k = i >> 4, hj = i & 15;
            *(float4*)&Ws[k][hj * 4] =
                *(const float4*)&Wm[(size_t)(k0 + k) * HH + h0 + hj * 4];
        }
        for (int i = t; i < BB * KC / 4; i += 256) {
            int b = i & 63, j = i >> 6;
            float4 p = *(const float4*)&inp[b * DIN + k0 + j * 4];
            Is[j * 4 + 0][b] = p.x;
            Is[j * 4 + 1][b] = p.y;
            Is[j * 4 + 2][b] = p.z;
            Is[j * 4 + 3][b] = p.w;
        }
        __syncthreads();

        int ty = t >> 4, tx = t & 15;          // 4 batches x 4 cols / thread
        float4 a0 = {0,0,0,0}, a1 = {0,0,0,0}, a2 = {0,0,0,0}, a3 = {0,0,0,0};
#pragma unroll 8
        for (int k = 0; k < KC; k++) {
            float4 ib = *(const float4*)&Is[k][ty * 4];
            float4 wv = *(const float4*)&Ws[k][tx * 4];
            a0.x = fmaf(ib.x, wv.x, a0.x); a0.y = fmaf(ib.x, wv.y, a0.y);
            a0.z = fmaf(ib.x, wv.z, a0.z); a0.w = fmaf(ib.x, wv.w, a0.w);
            a1.x = fmaf(ib.y, wv.x, a1.x); a1.y = fmaf(ib.y, wv.y, a1.y);
            a1.z = fmaf(ib.y, wv.z, a1.z); a1.w = fmaf(ib.y, wv.w, a1.w);
            a2.x = fmaf(ib.z, wv.x, a2.x); a2.y = fmaf(ib.z, wv.y, a2.y);
            a2.z = fmaf(ib.z, wv.z, a2.z); a2.w = fmaf(ib.z, wv.w, a2.w);
            a3.x = fmaf(ib.w, wv.x, a3.x); a3.y = fmaf(ib.w, wv.y, a3.y);
            a3.z = fmaf(ib.w, wv.z, a3.z); a3.w = fmaf(ib.w, wv.w, a3.w);
        }
        float* outb = g_xpart + (size_t)kc * (BB * HH) + h0 + tx * 4;
        *(float4*)&outb[(ty * 4 + 0) * HH] = a0;
        *(float4*)&outb[(ty * 4 + 1) * HH] = a1;
        *(float4*)&outb[(ty * 4 + 2) * HH] = a2;
        *(float4*)&outb[(ty * 4 + 3) * HH] = a3;
    } else {                                    // ---- mask canonicalize ----
        const unsigned* wds = (const unsigned*)mraw;
        int notInt = 0, notFloat = 0;
        for (int i = t; i < 1024; i += 256) {
            unsigned x = wds[i];
            notInt   |= (x > 1u);
            notFloat |= (x != 0u && x != 0x3F800000u);
        }
        notInt   = __syncthreads_or(notInt);
        notFloat = __syncthreads_or(notFloat);
        int mode = notInt ? (notFloat ? 2 : 1) : 0;  // 0:int32 1:float32 2:bytes

        int base = (blk - 128) * 2048;
        for (int i = base + t; i < base + 2048; i += 256) {
            unsigned char v;
            if (mode == 0)      v = (((const int*)mraw)[i] != 0);
            else if (mode == 1) v = (((const float*)mraw)[i] != 0.0f);
            else                v = (((const unsigned char*)mraw)[i] != 0);
            g_mask[i] = v;
        }
    }
}

// ---------------- kernel 1: reduce gemm partials + bias, reset counters -----
__global__ __launch_bounds__(256) void xreduce_kernel(const float* __restrict__ bias) {
    int i = blockIdx.x * 256 + threadIdx.x;     // float4 index, 16384 total
    if (i == 0) g_ticket = 0;
    if (i < BB) g_bdone[i] = 0;
    float4 s = *(const float4*)&bias[(i & 255) * 4];
    const float4* xp = (const float4*)g_xpart;
#pragma unroll
    for (int kc = 0; kc < KSPLIT; kc++) {
        float4 p = xp[kc * (BB * HH / 4) + i];
        s.x += p.x; s.y += p.y; s.z += p.z; s.w += p.w;
    }
    ((float4*)g_x)[i] = s;
}

// ---------------- kernel 2: fused scores+exp-sum+weighted sum+finalize ------
__device__ __forceinline__ void issue_row(const float* cb, int k, int n,
                                          unsigned slot_u32, int ln,
                                          const int* s_idx) {
    if (k < n) {
        const float* src = cb + (size_t)s_idx[k] * HH + ln * 4;
        unsigned dst = slot_u32 + ln * 16;
#pragma unroll
        for (int i = 0; i < 8; i++)
            asm volatile("cp.async.cg.shared.global [%0], [%1], 16;"
                         :: "r"(dst + i * 512), "l"(src + i * 128) : "memory");
    }
    asm volatile("cp.async.commit_group;" ::: "memory");
}

__global__ __launch_bounds__(512, 1) void pass1_kernel(const float* __restrict__ ctx,
                                                       const float* __restrict__ v,
                                                       float* __restrict__ out_applied,
                                                       float* __restrict__ out_w) {
    extern __shared__ float dsm[];
    float* xs   = dsm;                 // HH floats
    float* ring = dsm + HH;            // NWARP * RING_DEPTH * HH floats

    __shared__ int      s_idx[ROWS_PER_TILE];
    __shared__ int      s_wcnt[8];
    __shared__ float    s_l[NWARP];
    __shared__ unsigned s_tile;
    __shared__ int      s_last;

    int t  = threadIdx.x;
    int w  = t >> 5;
    int ln = t & 31;

    float4 vv[8];
    const float4* vr = (const float4*)v;
#pragma unroll
    for (int j = 0; j < 8; j++) vv[j] = __ldg(&vr[j * 32 + ln]);

    float* myring = ring + w * (RING_DEPTH * HH);
    unsigned ring_u32 = (unsigned)__cvta_generic_to_shared(myring);

    for (;;) {
        if (t == 0) s_tile = atomicAdd(&g_ticket, 1u);
        __syncthreads();               // also orders prior tile's smem reuse
        unsigned tile = s_tile;
        if (tile >= NTILES) break;

        int b  = tile >> 3;            // SPLITS = 8
        int sp = tile & (SPLITS - 1);
        int rowbase = b * SS + sp * ROWS_PER_TILE;

        xs[t]       = g_x[b * HH + t];
        xs[t + 512] = g_x[b * HH + 512 + t];

        // ---- compact unmasked row indices (deterministic order) ----
        unsigned char mk = 1;
        if (t < ROWS_PER_TILE) mk = g_mask[rowbase + t];
        unsigned bits = __ballot_sync(0xffffffffu, mk == 0);
        if (t < ROWS_PER_TILE && mk) g_score[rowbase + t] = NEG_INF;
        if (w < 8 && ln == 0) s_wcnt[w] = __popc(bits);
        __syncthreads();
        int n = 0;
#pragma unroll
        for (int i = 0; i < 8; i++) n += s_wcnt[i];
        if (t < ROWS_PER_TILE && !mk) {
            int basew = 0;
#pragma unroll
            for (int i = 0; i < 8; i++) if (i < w) basew += s_wcnt[i];
            s_idx[basew + __popc(bits & ((1u << ln) - 1u))] = t;
        }
        __syncthreads();

        // ---- per-warp row loop over compacted list ----
        float4 acc[8];
#pragma unroll
        for (int j = 0; j < 8; j++) acc[j] = make_float4(0.f, 0.f, 0.f, 0.f);
        float l = 0.f;

        const float* cb = ctx + (size_t)rowbase * HH;
        issue_row(cb, w,             n, ring_u32,          ln, s_idx);
        issue_row(cb, w + NWARP,     n, ring_u32 + HH * 4, ln, s_idx);
        issue_row(cb, w + 2 * NWARP, n, ring_u32 + HH * 8, ln, s_idx);
        int slot = 0;
        for (int k = w; k < n; k += NWARP) {
            asm volatile("cp.async.wait_group 2;" ::: "memory");
            const float* sp_ = myring + slot * HH;

            float part = 0.f;
#pragma unroll
            for (int j = 0; j < 8; j++) {
                float4 c  = *(const float4*)&sp_[j * 128 + ln * 4];
                float4 xj = *(const float4*)&xs[j * 128 + ln * 4];
                float4 vg = vv[j];
                part = fmaf(tanh_fast(xj.x + c.x), vg.x, part);
                part = fmaf(tanh_fast(xj.y + c.y), vg.y, part);
                part = fmaf(tanh_fast(xj.z + c.z), vg.z, part);
                part = fmaf(tanh_fast(xj.w + c.w), vg.w, part);
            }
#pragma unroll
            for (int off = 16; off; off >>= 1)
                part += __shfl_xor_sync(0xffffffffu, part, off);

            if (ln == 0) g_score[rowbase + s_idx[k]] = part;
            float p = __expf(part);    // fixed reference M=0: |score| < 40
            l += p;
#pragma unroll
            for (int j = 0; j < 8; j++) {
                float4 c = *(const float4*)&sp_[j * 128 + ln * 4];
                acc[j].x = fmaf(c.x, p, acc[j].x);
                acc[j].y = fmaf(c.y, p, acc[j].y);
                acc[j].z = fmaf(c.z, p, acc[j].z);
                acc[j].w = fmaf(c.w, p, acc[j].w);
            }
            issue_row(cb, k + 3 * NWARP, n, ring_u32 + slot * HH * 4, ln, s_idx);
            slot = (slot == RING_DEPTH - 1) ? 0 : slot + 1;
        }
        asm volatile("cp.async.wait_group 0;" ::: "memory");

        // ---- CTA combine: overlay acc onto ring smem, tree-reduce ----
        if (ln == 0) s_l[w] = l;
        __syncthreads();
        float* sout = ring;
#pragma unroll
        for (int j = 0; j < 8; j++)
            *(float4*)&sout[w * HH + j * 128 + ln * 4] = acc[j];
        __syncthreads();

        float L = 0.f;
#pragma unroll
        for (int i = 0; i < NWARP; i++) L += s_l[i];
        float sum0 = 0.f, sum1 = 0.f;
#pragma unroll
        for (int i = 0; i < NWARP; i++) {
            sum0 += sout[i * HH + t];
            sum1 += sout[i * HH + t + 512];
        }
        g_acc[(size_t)tile * HH + t]       = sum0;
        g_acc[(size_t)tile * HH + t + 512] = sum1;
        if (t == 0) g_l[tile] = L;

        // ---- last tile of this batch? then finalize the batch here ----
        __threadfence();
        if (t == 0) {
            unsigned old = atomicAdd(&g_bdone[b], 1u);
            s_last = (old == SPLITS - 1);
        }
        __syncthreads();
        if (s_last) {
            float Lb = 0.f;
#pragma unroll
            for (int i = 0; i < SPLITS; i++) Lb += __ldcg(&g_l[b * SPLITS + i]);
            float invL = 1.0f / Lb;
#pragma unroll
            for (int r = 0; r < 2; r++) {
                int h = t + r * 512;
                float s = 0.f;
#pragma unroll
                for (int i = 0; i < SPLITS; i++)
                    s += __ldcg(&g_acc[(size_t)(b * SPLITS + i) * HH + h]);
                out_applied[b * HH + h] = s * invL;
            }
#pragma unroll
            for (int r = 0; r < 4; r++) {
                int si = t + r * 512;
                float sc = __ldcg(&g_score[b * SS + si]);  // -inf masked -> 0
                out_w[b * SS + si] = __expf(sc) * invL;
            }
        }
        // top-of-loop __syncthreads orders smem reuse for the next tile
    }
}

// ---------------- launch ----------------
extern "C" void kernel_launch(void* const* d_in, const int* in_sizes, int n_in,
                              void* d_out, int out_size) {
    const float* inp  = (const float*)d_in[0];
    // d_in[1] = hidden (unused by the reference computation)
    const float* ctx  = (const float*)d_in[2];
    const void*  mask = d_in[3];
    const float* Wm   = (const float*)d_in[4];
    const float* bias = (const float*)d_in[5];
    const float* v    = (const float*)d_in[6];
    float* out = (float*)d_out;

    const int dyn_smem = (HH + NWARP * RING_DEPTH * HH) * (int)sizeof(float);
    cudaFuncSetAttribute(pass1_kernel,
                         cudaFuncAttributeMaxDynamicSharedMemorySize, dyn_smem);

    prologue_kernel<<<192, 256>>>(inp, Wm, mask);
    xreduce_kernel<<<BB * HH / 1024, 256>>>(bias);
    pass1_kernel<<<152, 512, dyn_smem>>>(ctx, v, out, out + BB * HH);
}